// round 1
// baseline (speedup 1.0000x reference)
#include <cuda_runtime.h>

// Problem constants (fixed by the reference module)
#define M_COUNT 20
#define R_COUNT 20
#define BATCH   400
#define STEPF   1e-4f

#define TPB 32            // one warp per block, one thread per sample
#define XSTRIDE 23        // per-thread shared stride (odd -> conflict-free)
#define ONE_SLOT 20       // per-thread slot holding constant 1.0f (pads single-substrate rate)
#define SCRATCH_SLOT 21   // per-thread dummy slot for padded (coef=0) updates

// ---------------------------------------------------------------------------
// Kernel 1: per-sample sequential reaction integration.
// One thread = one sample. State x[20] lives in shared (dynamic sparse index).
// Reaction metadata (substrate slots + <=4 signed-STEP update slots) is built
// once per block from sub/prod and broadcast-read (uniform LDS).
// ---------------------------------------------------------------------------
__global__ void __launch_bounds__(TPB)
sim_kernel(const float* __restrict__ x_in,
           const float* __restrict__ sub,
           const float* __restrict__ prd,
           const int*   __restrict__ niters,
           float*       __restrict__ x_out)
{
    __shared__ int   mi0[R_COUNT];
    __shared__ int   mi1[R_COUNT];
    __shared__ int   mu[R_COUNT][4];
    __shared__ float mv[R_COUNT][4];
    __shared__ float sx[TPB * XSTRIDE];

    const int tid = threadIdx.x;

    // --- build reaction metadata (lanes 0..19, one reaction each) ---
    if (tid < R_COUNT) {
        const int r = tid;
        int si0 = ONE_SLOT, si1 = ONE_SLOT, c = 0;
        #pragma unroll
        for (int m = 0; m < M_COUNT; ++m) {
            if (sub[r * M_COUNT + m] != 0.0f) {
                if (c == 0) si0 = m; else si1 = m;
                ++c;
            }
        }
        mi0[r] = si0;
        mi1[r] = si1;                    // stays ONE_SLOT if only one substrate

        int uc = 0;
        #pragma unroll
        for (int m = 0; m < M_COUNT; ++m) {
            float d = prd[r * M_COUNT + m] - sub[r * M_COUNT + m];
            if (d != 0.0f) { mu[r][uc] = m; mv[r][uc] = d * STEPF; ++uc; }
        }
        for (; uc < 4; ++uc) { mu[r][uc] = SCRATCH_SLOT; mv[r][uc] = 0.0f; }
    }
    __syncthreads();

    const int b = blockIdx.x * TPB + tid;
    if (b >= BATCH) return;

    const int base = tid * XSTRIDE;
    #pragma unroll
    for (int m = 0; m < M_COUNT; ++m) sx[base + m] = x_in[b * M_COUNT + m];
    sx[base + ONE_SLOT]     = 1.0f;
    sx[base + SCRATCH_SLOT] = 0.0f;

    // Reference gates each full iteration with (niter > i); once i >= niter the
    // state is frozen forever, so running exactly niter iterations is identical.
    const int n = niters[b];
    for (int it = 0; it < n; ++it) {
        #pragma unroll
        for (int r = 0; r < R_COUNT; ++r) {
            // rate = product of substrate concentrations (x * 1.0 pads exactly)
            const float rate = sx[base + mi0[r]] * sx[base + mi1[r]];
            #pragma unroll
            for (int k = 0; k < 4; ++k) {
                const int u = mu[r][k];
                sx[base + u] = fmaf(mv[r][k], rate, sx[base + u]);
            }
        }
    }

    #pragma unroll
    for (int m = 0; m < M_COUNT; ++m) x_out[b * M_COUNT + m] = sx[base + m];
}

// ---------------------------------------------------------------------------
// Kernel 2: correlation matrix of final x [400,20] -> c [20,20].
// Single block; whole tile (32 KB) staged in shared; two-pass (mean, center,
// norms, centered Gram) to match the reference numerics.
// ---------------------------------------------------------------------------
#define CTHREADS 512

__global__ void __launch_bounds__(CTHREADS)
corr_kernel(const float* __restrict__ xg, float* __restrict__ cout)
{
    __shared__ float xs[BATCH * M_COUNT];   // 32000 B
    __shared__ float psum[M_COUNT * 16];
    __shared__ float mean[M_COUNT];
    __shared__ float rn[M_COUNT];

    const int t = threadIdx.x;

    for (int i = t; i < BATCH * M_COUNT; i += CTHREADS) xs[i] = xg[i];
    __syncthreads();

    // column sums (20 cols x 16 chunks of 25 samples)
    if (t < M_COUNT * 16) {
        const int m = t / 16, ch = t % 16;
        float s = 0.0f;
        #pragma unroll 5
        for (int b = ch * 25; b < ch * 25 + 25; ++b) s += xs[b * M_COUNT + m];
        psum[t] = s;
    }
    __syncthreads();
    if (t < M_COUNT) {
        float s = 0.0f;
        #pragma unroll
        for (int c = 0; c < 16; ++c) s += psum[t * 16 + c];
        mean[t] = s * (1.0f / (float)BATCH);
    }
    __syncthreads();

    // center in place
    for (int i = t; i < BATCH * M_COUNT; i += CTHREADS) xs[i] -= mean[i % M_COUNT];
    __syncthreads();

    // column squared norms -> rsqrt
    if (t < M_COUNT * 16) {
        const int m = t / 16, ch = t % 16;
        float s = 0.0f;
        #pragma unroll 5
        for (int b = ch * 25; b < ch * 25 + 25; ++b) {
            const float v = xs[b * M_COUNT + m];
            s = fmaf(v, v, s);
        }
        psum[t] = s;
    }
    __syncthreads();
    if (t < M_COUNT) {
        float s = 0.0f;
        #pragma unroll
        for (int c = 0; c < 16; ++c) s += psum[t * 16 + c];
        rn[t] = rsqrtf(s);
    }
    __syncthreads();

    // centered Gram: one thread per (i,j) output element
    if (t < M_COUNT * M_COUNT) {
        const int i = t / M_COUNT, j = t % M_COUNT;
        float s = 0.0f;
        #pragma unroll 4
        for (int b = 0; b < BATCH; ++b)
            s = fmaf(xs[b * M_COUNT + i], xs[b * M_COUNT + j], s);
        cout[t] = s * rn[i] * rn[j];
    }
}

// ---------------------------------------------------------------------------
// Launch: inputs in metadata order: x[8000] f32, sub[400] f32, prod[400] f32,
// iterations_for_sample[400] i32. Output: x (8000 f32) then c (400 f32).
// Graph-capturable: two plain kernel launches, no allocs, no syncs.
// ---------------------------------------------------------------------------
extern "C" void kernel_launch(void* const* d_in, const int* in_sizes, int n_in,
                              void* d_out, int out_size)
{
    const float* x   = (const float*)d_in[0];
    const float* sub = (const float*)d_in[1];
    const float* prd = (const float*)d_in[2];
    const int*   it  = (const int*)  d_in[3];
    float* out = (float*)d_out;

    sim_kernel<<<(BATCH + TPB - 1) / TPB, TPB>>>(x, sub, prd, it, out);
    corr_kernel<<<1, CTHREADS>>>(out, out + BATCH * M_COUNT);
}

// round 2
// speedup vs baseline: 3.1122x; 3.1122x over previous
#include <cuda_runtime.h>

// Problem constants (fixed by the reference module)
#define M_COUNT 20
#define R_COUNT 20
#define BATCH   400
#define STEPF   1e-4f

#define ONE_LANE 20            // lane holding constant 1.0f (pads single-substrate rate)
#define FULLMASK 0xFFFFFFFFu

// ---------------------------------------------------------------------------
// Kernel 1: warp-per-sample reaction integration, state in registers.
// Lane m (< 20) holds x[m]; lane 20 holds 1.0f. Dynamic substrate indexing is
// done with __shfl_sync. Update: every lane does xv += coef[r]*rate, where
// coef = STEP*(prod-sub) per lane (0 for untouched lanes -> exact identity).
// All metadata (i0/i1 uniform ints, 20 coefs) lives in registers (full unroll).
// ---------------------------------------------------------------------------
__global__ void __launch_bounds__(32)
sim_kernel(const float* __restrict__ x_in,
           const float* __restrict__ sub,
           const float* __restrict__ prd,
           const int*   __restrict__ niters,
           float*       __restrict__ x_out)
{
    const int lane = threadIdx.x;
    const int s    = blockIdx.x;            // one warp (block) per sample

    // --- build reaction metadata in registers ---
    float coef[R_COUNT];
    int   i0[R_COUNT], i1[R_COUNT];
    #pragma unroll
    for (int r = 0; r < R_COUNT; ++r) {
        float sv = 0.0f, pv = 0.0f;
        if (lane < M_COUNT) {
            sv = sub[r * M_COUNT + lane];
            pv = prd[r * M_COUNT + lane];
        }
        coef[r] = (pv - sv) * STEPF;        // 0 for lanes >= 20
        unsigned mask = __ballot_sync(FULLMASK, sv != 0.0f);
        if (mask) {
            i0[r] = __ffs(mask) - 1;
            unsigned m2 = mask & (mask - 1);
            i1[r] = m2 ? (__ffs(m2) - 1) : ONE_LANE;   // single substrate -> pad with 1.0
        } else {
            i0[r] = ONE_LANE;               // empty row -> rate = 1.0 (matches prod(x^0))
            i1[r] = ONE_LANE;
        }
    }

    // --- state ---
    float xv;
    if (lane < M_COUNT)       xv = x_in[s * M_COUNT + lane];
    else if (lane == ONE_LANE) xv = 1.0f;
    else                      xv = 0.0f;

    // Reference freezes a sample once i >= niter, so running exactly niter
    // full iterations is identical.
    const int n = niters[s];
    for (int it = 0; it < n; ++it) {
        #pragma unroll
        for (int r = 0; r < R_COUNT; ++r) {
            const float v0   = __shfl_sync(FULLMASK, xv, i0[r]);
            const float v1   = __shfl_sync(FULLMASK, xv, i1[r]);
            const float rate = v0 * v1;                 // law of mass action
            xv = fmaf(coef[r], rate, xv);               // sparse update, exact for coef=0
        }
    }

    if (lane < M_COUNT) x_out[s * M_COUNT + lane] = xv;
}

// ---------------------------------------------------------------------------
// Kernel 2: correlation matrix, one block per output ROW (20 blocks).
// Each block stages the full [400,20] tile in shared, redundantly computes all
// means and inverse norms (cheap), then its own centered-Gram row. No atomics,
// no cross-block deps, deterministic.
// ---------------------------------------------------------------------------
#define CB_THREADS 320          // 20 columns x 16 batch-chunks of 25

__global__ void __launch_bounds__(CB_THREADS)
corr_kernel(const float* __restrict__ xg, float* __restrict__ cout)
{
    __shared__ float xs[BATCH * M_COUNT];   // 32000 B
    __shared__ float ps[CB_THREADS];
    __shared__ float mean_s[M_COUNT];
    __shared__ float rn_s[M_COUNT];

    const int t = threadIdx.x;
    const int i = blockIdx.x;               // output row

    for (int k = t; k < BATCH * M_COUNT; k += CB_THREADS) xs[k] = xg[k];
    __syncthreads();

    const int j  = t / 16;                  // column 0..19
    const int ch = t % 16;                  // batch chunk 0..15 (25 samples each)
    const int b0 = ch * 25;

    // column means
    {
        float s = 0.0f;
        #pragma unroll 5
        for (int b = b0; b < b0 + 25; ++b) s += xs[b * M_COUNT + j];
        ps[t] = s;
    }
    __syncthreads();
    if (t < M_COUNT) {
        float s = 0.0f;
        #pragma unroll
        for (int c = 0; c < 16; ++c) s += ps[t * 16 + c];
        mean_s[t] = s * (1.0f / (float)BATCH);
    }
    __syncthreads();

    // column inverse norms (of centered columns)
    {
        const float mj = mean_s[j];
        float s = 0.0f;
        #pragma unroll 5
        for (int b = b0; b < b0 + 25; ++b) {
            const float v = xs[b * M_COUNT + j] - mj;
            s = fmaf(v, v, s);
        }
        ps[t] = s;
    }
    __syncthreads();
    if (t < M_COUNT) {
        float s = 0.0f;
        #pragma unroll
        for (int c = 0; c < 16; ++c) s += ps[t * 16 + c];
        rn_s[t] = rsqrtf(s);
    }
    __syncthreads();

    // row i of the centered Gram, scaled
    {
        const float mi = mean_s[i];
        const float mj = mean_s[j];
        float s = 0.0f;
        #pragma unroll 5
        for (int b = b0; b < b0 + 25; ++b) {
            const float vi = xs[b * M_COUNT + i] - mi;
            const float vj = xs[b * M_COUNT + j] - mj;
            s = fmaf(vi, vj, s);
        }
        ps[t] = s;
    }
    __syncthreads();
    if (t < M_COUNT) {
        float s = 0.0f;
        #pragma unroll
        for (int c = 0; c < 16; ++c) s += ps[t * 16 + c];
        cout[i * M_COUNT + t] = s * rn_s[i] * rn_s[t];
    }
}

// ---------------------------------------------------------------------------
// Launch. Inputs (metadata order): x[8000] f32, sub[400] f32, prod[400] f32,
// iterations_for_sample[400] i32. Output: x (8000 f32) then c (400 f32).
// Graph-capturable: two plain launches, no allocs, no syncs.
// ---------------------------------------------------------------------------
extern "C" void kernel_launch(void* const* d_in, const int* in_sizes, int n_in,
                              void* d_out, int out_size)
{
    const float* x   = (const float*)d_in[0];
    const float* sub = (const float*)d_in[1];
    const float* prd = (const float*)d_in[2];
    const int*   it  = (const int*)  d_in[3];
    float* out = (float*)d_out;

    sim_kernel<<<BATCH, 32>>>(x, sub, prd, it, out);
    corr_kernel<<<M_COUNT, CB_THREADS>>>(out, out + BATCH * M_COUNT);
}